// round 6
// baseline (speedup 1.0000x reference)
#include <cuda_runtime.h>
#include <math.h>

// Fixed-shape problem: B=4096, V=32000, fp32
#define VDIM   32000
#define NV4    (VDIM / 4)      // 8000
#define BMAX   4096
#define CAP    2048            // global candidate capacity per row (~516 expected)
#define ATHR   256             // rowprep threads
#define NWARP_A (ATHR / 32)
#define TCAP   33              // per-thread SMEM buffer (stride 33 -> conflict-free)
#define BTHR   128             // bisect threads (4 warps, 1 row/warp)
#define WPB    (BTHR / 32)
#define FULLM  0xffffffffu

__device__ float    g_cand[(size_t)BMAX * CAP];
__device__ int      g_cnt[BMAX];
__device__ float    g_max[BMAX];   // raw-X row max
__device__ float    g_tx[BMAX];
__device__ float    g_rowloss[BMAX];
__device__ unsigned g_ticket;

__global__ void init_kernel() { g_ticket = 0u; }

// Thread-local in-place compaction keeping v > thr (reads ahead of writes).
__device__ __forceinline__ int tprune(float* tb, int cnt, float thr)
{
    int nc = 0;
    for (int i = 0; i < cnt; ++i) { float v = tb[i]; if (v > thr) tb[nc++] = v; }
    return nc;
}

#define DEP(v) do { float _v = (v); if (_v > thr) { if (cnt < TCAP) tb[cnt++] = _v; } } while (0)

// ---------------------------------------------------------------------------
// Kernel 1: persistent CTAs, global ticket per row. Single streaming pass,
// unrolled x2 with loads batched first (MLP=4/warp). Per-thread SMEM buffers
// collect a superset of candidates (x > warp-running-maxX - 2); exact final
// filter with rowmaxX - 2, then deterministic block-scan writeout.
// ---------------------------------------------------------------------------
__global__ __launch_bounds__(ATHR) void rowprep_kernel(
    const float* __restrict__ logits, const float* __restrict__ targets, int B)
{
    __shared__ float s_tb[ATHR * TCAP];        // ~33 KB, stride-33
    __shared__ float s_m[NWARP_A], s_t[NWARP_A];
    __shared__ float s_bc[1];
    __shared__ int   s_wsum[NWARP_A];
    __shared__ int   s_wbase[NWARP_A + 1];
    __shared__ int   s_row;

    const int t    = threadIdx.x;
    const int lane = t & 31;
    const int wid  = t >> 5;
    float* tb = s_tb + t * TCAP;

    for (;;) {
        if (t == 0) s_row = (int)atomicAdd(&g_ticket, 1u);
        __syncthreads();
        const int r = s_row;
        if (r >= B) return;

        const float4* __restrict__ lg = reinterpret_cast<const float4*>(logits  + (size_t)r * VDIM);
        const float4* __restrict__ tg = reinterpret_cast<const float4*>(targets + (size_t)r * VDIM);

        float thr  = -INFINITY;
        float lmax = -INFINITY;
        float tx0 = 0.0f, tx1 = 0.0f;
        int   cnt = 0;

        for (int j = t; j < NV4; j += 2 * ATHR) {
            const bool two = (j + ATHR < NV4);   // warp-uniform
            // ---- batch loads first (MLP) ----
            float4 xa = __ldcs(&lg[j]);
            float4 ta = __ldcs(&tg[j]);
            float4 xb = make_float4(-INFINITY, -INFINITY, -INFINITY, -INFINITY);
            float4 tb4 = make_float4(0.f, 0.f, 0.f, 0.f);
            if (two) {
                xb  = __ldcs(&lg[j + ATHR]);
                tb4 = __ldcs(&tg[j + ATHR]);
            }

            // ---- running max incl. current batch -> tight threshold ----
            lmax = fmaxf(lmax, fmaxf(fmaxf(fmaxf(xa.x, xa.y), fmaxf(xa.z, xa.w)),
                                     fmaxf(fmaxf(xb.x, xb.y), fmaxf(xb.z, xb.w))));
            float wm = lmax;
            #pragma unroll
            for (int o = 16; o; o >>= 1)
                wm = fmaxf(wm, __shfl_xor_sync(FULLM, wm, o));
            thr = wm - 2.0f;

            // ---- sum(t*X) ----
            tx0 = fmaf(ta.x, xa.x, tx0);
            tx1 = fmaf(ta.y, xa.y, tx1);
            tx0 = fmaf(ta.z, xa.z, tx0);
            tx1 = fmaf(ta.w, xa.w, tx1);
            if (two) {
                tx0 = fmaf(tb4.x, xb.x, tx0);
                tx1 = fmaf(tb4.y, xb.y, tx1);
                tx0 = fmaf(tb4.z, xb.z, tx0);
                tx1 = fmaf(tb4.w, xb.w, tx1);
            }

            // ---- thread-local safety prune ----
            if (cnt > TCAP - 9) cnt = tprune(tb, cnt, thr);

            // ---- thread-local deposits (no warp coordination) ----
            DEP(xa.x); DEP(xa.y); DEP(xa.z); DEP(xa.w);
            if (two) { DEP(xb.x); DEP(xb.y); DEP(xb.z); DEP(xb.w); }
        }

        // ---- block reductions: exact row max (raw X), sum(t*X) ----
        float tx = tx0 + tx1;
        float wm = lmax;
        #pragma unroll
        for (int o = 16; o; o >>= 1) {
            wm = fmaxf(wm, __shfl_xor_sync(FULLM, wm, o));
            tx += __shfl_xor_sync(FULLM, tx, o);
        }
        if (lane == 0) { s_m[wid] = wm; s_t[wid] = tx; }
        __syncthreads();
        if (t == 0) {
            float m = s_m[0], s = s_t[0];
            for (int w = 1; w < NWARP_A; ++w) { m = fmaxf(m, s_m[w]); s += s_t[w]; }
            s_bc[0] = m;
            g_max[r] = m;
            g_tx[r]  = s;
        }
        __syncthreads();
        const float thrF = s_bc[0] - 2.0f;

        // ---- exact final filter (thread-local) ----
        cnt = tprune(tb, cnt, thrF);

        // ---- block exclusive scan over 256 counts ----
        int incl = cnt;
        #pragma unroll
        for (int o = 1; o < 32; o <<= 1) {
            int v = __shfl_up_sync(FULLM, incl, o);
            if (lane >= o) incl += v;
        }
        if (lane == 31) s_wsum[wid] = incl;
        __syncthreads();
        if (t == 0) {
            int run = 0;
            for (int w = 0; w < NWARP_A; ++w) { s_wbase[w] = run; run += s_wsum[w]; }
            s_wbase[NWARP_A] = run;
            g_cnt[r] = run < CAP ? run : CAP;
        }
        __syncthreads();

        // ---- deterministic writeout (thread order, element order) ----
        int base = s_wbase[wid] + (incl - cnt);
        float* __restrict__ outc = g_cand + (size_t)r * CAP;
        for (int i = 0; i < cnt; ++i) {
            int p = base + i;
            if (p < CAP) outc[p] = tb[i];
        }
        __syncthreads();   // protect s_row / buffers before next row
    }
}

// ---------------------------------------------------------------------------
// Kernel 2: bisection over candidates only (one warp per row). Candidates
// stored as raw X; convert with exact *0.5 at load. Mirrors the reference
// update rule (f_m * f_lo >= 0, last tau_m).
// ---------------------------------------------------------------------------
__global__ __launch_bounds__(BTHR) void bisect_kernel(int B)
{
    __shared__ float s_c[WPB * CAP];          // 32 KB
    const int lane = threadIdx.x & 31;
    const int wid  = threadIdx.x >> 5;
    const int r    = blockIdx.x * WPB + wid;
    if (r >= B) return;

    float* cs = s_c + wid * CAP;
    const int n = g_cnt[r];
    const float* __restrict__ gc = g_cand + (size_t)r * CAP;
    for (int i = lane; i < n; i += 32) cs[i] = 0.5f * gc[i];
    __syncwarp();

    const float mx     = 0.5f * g_max[r];       // exact: matches reference max(Xs)
    float       tau_lo = mx - 1.0f;
    const float tau_hi = mx - 0.00559016994f;   // (1/32000)^(alpha-1), alpha=1.5
    float       dm     = tau_hi - tau_lo;

    float acc = 0.0f;
    for (int i = lane; i < n; i += 32) {
        float d = fmaxf(cs[i] - tau_lo, 0.0f);
        acc = fmaf(d, d, acc);
    }
    #pragma unroll
    for (int o = 16; o; o >>= 1) acc += __shfl_xor_sync(FULLM, acc, o);
    const float f_lo = acc - 1.0f;

    float tau_m = tau_lo;
    for (int itr = 0; itr < 50; ++itr) {
        dm *= 0.5f;
        tau_m = tau_lo + dm;
        if (tau_m == tau_lo) break;   // fp32 fixed point: rest are no-ops
        float a = 0.0f;
        for (int i = lane; i < n; i += 32) {
            float d = fmaxf(cs[i] - tau_m, 0.0f);
            a = fmaf(d, d, a);
        }
        #pragma unroll
        for (int o = 16; o; o >>= 1) a += __shfl_xor_sync(FULLM, a, o);
        float f_m = a - 1.0f;
        if (f_m * f_lo >= 0.0f) tau_lo = tau_m;
    }

    float s2 = 0.0f, s3 = 0.0f, sx = 0.0f;
    for (int i = lane; i < n; i += 32) {
        float xs = cs[i];
        float z  = fmaxf(xs - tau_m, 0.0f);
        float z2 = z * z;
        s2 += z2;
        s3 = fmaf(z2, z,  s3);
        sx = fmaf(z2, xs, sx);
    }
    #pragma unroll
    for (int o = 16; o; o >>= 1) {
        s2 += __shfl_xor_sync(FULLM, s2, o);
        s3 += __shfl_xor_sync(FULLM, s3, o);
        sx += __shfl_xor_sync(FULLM, sx, o);
    }
    if (lane == 0) {
        float omega = (1.0f - s3 / (s2 * sqrtf(s2))) * (4.0f / 3.0f);
        g_rowloss[r] = omega + 2.0f * sx / s2 - g_tx[r];
    }
}

// ---------------------------------------------------------------------------
// Kernel 3: mean over rows.
// ---------------------------------------------------------------------------
__global__ void reduce_kernel(float* __restrict__ out, int B)
{
    __shared__ float s[1024];
    float a = 0.0f;
    for (int i = threadIdx.x; i < B; i += 1024) a += g_rowloss[i];
    s[threadIdx.x] = a;
    __syncthreads();
    #pragma unroll
    for (int o = 512; o; o >>= 1) {
        if (threadIdx.x < o) s[threadIdx.x] += s[threadIdx.x + o];
        __syncthreads();
    }
    if (threadIdx.x == 0) out[0] = s[0] / (float)B;
}

extern "C" void kernel_launch(void* const* d_in, const int* in_sizes, int n_in,
                              void* d_out, int out_size)
{
    const float* logits  = (const float*)d_in[0];
    const float* targets = (const float*)d_in[1];
    int B = in_sizes[0] / VDIM;
    if (B > BMAX) B = BMAX;

    int dev = 0, sms = 148, perSM = 0;
    cudaGetDevice(&dev);
    cudaDeviceGetAttribute(&sms, cudaDevAttrMultiProcessorCount, dev);
    cudaOccupancyMaxActiveBlocksPerMultiprocessor(&perSM, rowprep_kernel, ATHR, 0);
    if (perSM < 1) perSM = 1;
    int grid = sms * perSM;
    if (grid > B) grid = B;

    init_kernel<<<1, 1>>>();
    rowprep_kernel<<<grid, ATHR>>>(logits, targets, B);
    bisect_kernel<<<(B + WPB - 1) / WPB, BTHR>>>(B);
    reduce_kernel<<<1, 1024>>>((float*)d_out, B);
}